// round 14
// baseline (speedup 1.0000x reference)
#include <cuda_runtime.h>
#include <cuda_bf16.h>

// Dataset: N_NODES = 1e6, N_EDGES = 32e6, edge_index int32 (JAX x64-off downcast).
//
// FINAL converged design (best: 463.3us; reproduced R8/R11/R12/R13):
//   - Two scatter-add passes at ~95% of the path-independent LTS cap
//     (~6300 B/cyc). Per pass: 0.25GB coalesced index stream (only DRAM
//     traffic, 14.6%) + ~1GB random gather sectors + ~1GB RED sectors,
//     all L2-resident (x/agg 4MB each; L2 126MB). issue=4%, occ=80%.
//   - Runtime ~= 1.05x LTS-traffic floor + ~15us fixed.
//   - Falsified/rejected (measured or costed):
//       src-bucket partition R3:606us; dst counting-sort R4:542us;
//       smem accumulation (ATOMS 2cyc/lane > REDG 1.29);
//       8-edge unroll+__ldcg R5:475us; L1 carveout R9: neutral;
//       block 256 vs 512 R11: tie; 40b packing (prep > savings);
//       warp dedup (0.05% collisions); coop-launch reuse (no persistence);
//       pass fusion (relu breaks linearity); fp16 gathers (sector-count
//       invariant); sigmoid-saturation shortcut (data-blind, incorrect).
#define MAX_NODES 1000000
#define SCATTER_THREADS 512

// Single scratch region so one memset node covers both buffers.
__device__ float g_agg[2 * MAX_NODES];

// ---------------------------------------------------------------------------
// Scatter-add pass: 4 edges/thread, exactly one iteration per thread.
//   RELU_W == false: agg[dst] += vals[src]
//   RELU_W == true : agg[dst] += max(vals[src]*w, 0)
// Index stream via __ldcs (read-once, keep x/agg L2-resident); gathers via
// __ldg (~6-11% free L1 hits); atomicAdd w/ unused result -> REDG (no return).
// ---------------------------------------------------------------------------
template <bool RELU_W>
__global__ __launch_bounds__(SCATTER_THREADS)
void scatter_kernel(const int4* __restrict__ src4,
                    const int4* __restrict__ dst4,
                    const float* __restrict__ vals,
                    const float* __restrict__ wptr,
                    float* __restrict__ agg,
                    int n_quads, int n_edges) {
    const float w = RELU_W ? __ldg(wptr) : 0.0f;

    int tid = blockIdx.x * blockDim.x + threadIdx.x;
    int stride = gridDim.x * blockDim.x;

    for (int i = tid; i < n_quads; i += stride) {
        int4 s = __ldcs(&src4[i]);
        int4 d = __ldcs(&dst4[i]);

        float v0 = __ldg(&vals[s.x]);
        float v1 = __ldg(&vals[s.y]);
        float v2 = __ldg(&vals[s.z]);
        float v3 = __ldg(&vals[s.w]);
        if (RELU_W) {
            v0 = fmaxf(v0 * w, 0.0f);
            v1 = fmaxf(v1 * w, 0.0f);
            v2 = fmaxf(v2 * w, 0.0f);
            v3 = fmaxf(v3 * w, 0.0f);
        }
        atomicAdd(&agg[d.x], v0);
        atomicAdd(&agg[d.y], v1);
        atomicAdd(&agg[d.z], v2);
        atomicAdd(&agg[d.w], v3);
    }

    // tail (only if n_edges % 4 != 0; dataset: never)
    const int* src = (const int*)src4;
    const int* dst = (const int*)dst4;
    for (int e = (n_quads << 2) + tid; e < n_edges; e += stride) {
        float t = __ldg(&vals[src[e]]);
        if (RELU_W) t = fmaxf(t * w, 0.0f);
        atomicAdd(&agg[dst[e]], t);
    }
}

// ---------------------------------------------------------------------------
// epilogue: out = sigmoid(relu(agg2 * w2)), float4-vectorized
// ---------------------------------------------------------------------------
__global__ __launch_bounds__(256)
void epilogue_kernel(const float* __restrict__ w2ptr,
                     const float* __restrict__ agg2,
                     float* __restrict__ out, int n) {
    const float w2 = __ldg(w2ptr);
    int i = blockIdx.x * blockDim.x + threadIdx.x;
    int stride = gridDim.x * blockDim.x;

    const float4* a4 = reinterpret_cast<const float4*>(agg2);
    float4* o4 = reinterpret_cast<float4*>(out);
    int n4 = n >> 2;
    for (int j = i; j < n4; j += stride) {
        float4 a = a4[j];
        float4 r;
        r.x = 1.0f / (1.0f + __expf(-fmaxf(a.x * w2, 0.0f)));
        r.y = 1.0f / (1.0f + __expf(-fmaxf(a.y * w2, 0.0f)));
        r.z = 1.0f / (1.0f + __expf(-fmaxf(a.z * w2, 0.0f)));
        r.w = 1.0f / (1.0f + __expf(-fmaxf(a.w * w2, 0.0f)));
        o4[j] = r;
    }
    for (int j = (n4 << 2) + i; j < n; j += stride) {
        float h = fmaxf(agg2[j] * w2, 0.0f);
        out[j] = 1.0f / (1.0f + __expf(-h));
    }
}

// ---------------------------------------------------------------------------
extern "C" void kernel_launch(void* const* d_in, const int* in_sizes, int n_in,
                              void* d_out, int out_size) {
    const float* x  = (const float*)d_in[0];
    const int* ei   = (const int*)d_in[1];
    const float* w1 = (const float*)d_in[2];
    const float* w2 = (const float*)d_in[3];
    float* out = (float*)d_out;

    const int n_nodes = in_sizes[0];
    const int n_edges = in_sizes[1] / 2;
    const int4* src4 = (const int4*)ei;
    const int4* dst4 = (const int4*)(ei + n_edges);

    float* aggbase;
    cudaGetSymbolAddress((void**)&aggbase, g_agg);
    float* agg1 = aggbase;
    float* agg2 = aggbase + MAX_NODES;

    // 1) zero both scratch buffers with ONE memset node
    cudaMemsetAsync(aggbase, 0, (size_t)2 * MAX_NODES * sizeof(float));

    // scatter grid: 4 edges/thread, exactly one iteration per thread
    const int threads = SCATTER_THREADS;
    int n_quads = n_edges >> 2;
    long long want = ((long long)n_quads + threads - 1) / threads;
    int blocks = (int)(want > 1048576LL ? 1048576LL : want);
    if (blocks < 1) blocks = 1;

    // 2) pass 1: agg1[dst] += x[src]
    scatter_kernel<false><<<blocks, threads>>>(src4, dst4, x, w1, agg1,
                                               n_quads, n_edges);

    // 3) pass 2: agg2[dst] += relu(agg1[src] * w1)
    scatter_kernel<true><<<blocks, threads>>>(src4, dst4, agg1, w1, agg2,
                                              n_quads, n_edges);

    // 4) epilogue (vectorized)
    {
        int eblocks = ((n_nodes >> 2) + 255) / 256;
        if (eblocks > 2048) eblocks = 2048;
        if (eblocks < 1) eblocks = 1;
        epilogue_kernel<<<eblocks, 256>>>(w2, agg2, out, n_nodes);
    }
}

// round 15
// speedup vs baseline: 1.0024x; 1.0024x over previous
#include <cuda_runtime.h>
#include <cuda_bf16.h>

// Dataset: N_NODES = 1e6, N_EDGES = 32e6, edge_index int32 (JAX x64-off downcast).
//
// FINAL converged design (best: 463.3us; reproduced R8/R11/R12/R13/R14):
//   - Two scatter-add passes at ~95% of the path-independent LTS cap
//     (~6300 B/cyc). Per pass: 0.25GB coalesced index stream (only DRAM
//     traffic, 14.6%) + ~1GB random gather sectors + ~1GB RED sectors,
//     all L2-resident (x/agg 4MB each; L2 126MB). issue=4%, occ=80%.
//   - Runtime ~= 1.05x LTS-traffic floor + ~15us fixed.
//   - Falsified/rejected (measured or costed):
//       src-bucket partition R3:606us; dst counting-sort R4:542us;
//       smem accumulation (ATOMS 2cyc/lane > REDG 1.29);
//       8-edge unroll+__ldcg R5:475us; L1 carveout R9: neutral;
//       block 256 vs 512 R11: tie; 40b packing (prep > savings);
//       warp dedup (0.05% collisions); coop-launch reuse (no persistence);
//       pass fusion (relu breaks linearity); fp16 gathers (sector-count
//       invariant); vector atomics (random dsts); TMA index loads (same
//       LTS cap); sigmoid-saturation shortcut (data-blind, incorrect).
#define MAX_NODES 1000000
#define SCATTER_THREADS 512

// Single scratch region so one memset node covers both buffers.
__device__ float g_agg[2 * MAX_NODES];

// ---------------------------------------------------------------------------
// Scatter-add pass: 4 edges/thread, exactly one iteration per thread.
//   RELU_W == false: agg[dst] += vals[src]
//   RELU_W == true : agg[dst] += max(vals[src]*w, 0)
// Index stream via __ldcs (read-once, keep x/agg L2-resident); gathers via
// __ldg (~6-11% free L1 hits); atomicAdd w/ unused result -> REDG (no return).
// ---------------------------------------------------------------------------
template <bool RELU_W>
__global__ __launch_bounds__(SCATTER_THREADS)
void scatter_kernel(const int4* __restrict__ src4,
                    const int4* __restrict__ dst4,
                    const float* __restrict__ vals,
                    const float* __restrict__ wptr,
                    float* __restrict__ agg,
                    int n_quads, int n_edges) {
    const float w = RELU_W ? __ldg(wptr) : 0.0f;

    int tid = blockIdx.x * blockDim.x + threadIdx.x;
    int stride = gridDim.x * blockDim.x;

    for (int i = tid; i < n_quads; i += stride) {
        int4 s = __ldcs(&src4[i]);
        int4 d = __ldcs(&dst4[i]);

        float v0 = __ldg(&vals[s.x]);
        float v1 = __ldg(&vals[s.y]);
        float v2 = __ldg(&vals[s.z]);
        float v3 = __ldg(&vals[s.w]);
        if (RELU_W) {
            v0 = fmaxf(v0 * w, 0.0f);
            v1 = fmaxf(v1 * w, 0.0f);
            v2 = fmaxf(v2 * w, 0.0f);
            v3 = fmaxf(v3 * w, 0.0f);
        }
        atomicAdd(&agg[d.x], v0);
        atomicAdd(&agg[d.y], v1);
        atomicAdd(&agg[d.z], v2);
        atomicAdd(&agg[d.w], v3);
    }

    // tail (only if n_edges % 4 != 0; dataset: never)
    const int* src = (const int*)src4;
    const int* dst = (const int*)dst4;
    for (int e = (n_quads << 2) + tid; e < n_edges; e += stride) {
        float t = __ldg(&vals[src[e]]);
        if (RELU_W) t = fmaxf(t * w, 0.0f);
        atomicAdd(&agg[dst[e]], t);
    }
}

// ---------------------------------------------------------------------------
// epilogue: out = sigmoid(relu(agg2 * w2)), float4-vectorized
// ---------------------------------------------------------------------------
__global__ __launch_bounds__(256)
void epilogue_kernel(const float* __restrict__ w2ptr,
                     const float* __restrict__ agg2,
                     float* __restrict__ out, int n) {
    const float w2 = __ldg(w2ptr);
    int i = blockIdx.x * blockDim.x + threadIdx.x;
    int stride = gridDim.x * blockDim.x;

    const float4* a4 = reinterpret_cast<const float4*>(agg2);
    float4* o4 = reinterpret_cast<float4*>(out);
    int n4 = n >> 2;
    for (int j = i; j < n4; j += stride) {
        float4 a = a4[j];
        float4 r;
        r.x = 1.0f / (1.0f + __expf(-fmaxf(a.x * w2, 0.0f)));
        r.y = 1.0f / (1.0f + __expf(-fmaxf(a.y * w2, 0.0f)));
        r.z = 1.0f / (1.0f + __expf(-fmaxf(a.z * w2, 0.0f)));
        r.w = 1.0f / (1.0f + __expf(-fmaxf(a.w * w2, 0.0f)));
        o4[j] = r;
    }
    for (int j = (n4 << 2) + i; j < n; j += stride) {
        float h = fmaxf(agg2[j] * w2, 0.0f);
        out[j] = 1.0f / (1.0f + __expf(-h));
    }
}

// ---------------------------------------------------------------------------
extern "C" void kernel_launch(void* const* d_in, const int* in_sizes, int n_in,
                              void* d_out, int out_size) {
    const float* x  = (const float*)d_in[0];
    const int* ei   = (const int*)d_in[1];
    const float* w1 = (const float*)d_in[2];
    const float* w2 = (const float*)d_in[3];
    float* out = (float*)d_out;

    const int n_nodes = in_sizes[0];
    const int n_edges = in_sizes[1] / 2;
    const int4* src4 = (const int4*)ei;
    const int4* dst4 = (const int4*)(ei + n_edges);

    float* aggbase;
    cudaGetSymbolAddress((void**)&aggbase, g_agg);
    float* agg1 = aggbase;
    float* agg2 = aggbase + MAX_NODES;

    // 1) zero both scratch buffers with ONE memset node
    cudaMemsetAsync(aggbase, 0, (size_t)2 * MAX_NODES * sizeof(float));

    // scatter grid: 4 edges/thread, exactly one iteration per thread
    const int threads = SCATTER_THREADS;
    int n_quads = n_edges >> 2;
    long long want = ((long long)n_quads + threads - 1) / threads;
    int blocks = (int)(want > 1048576LL ? 1048576LL : want);
    if (blocks < 1) blocks = 1;

    // 2) pass 1: agg1[dst] += x[src]
    scatter_kernel<false><<<blocks, threads>>>(src4, dst4, x, w1, agg1,
                                               n_quads, n_edges);

    // 3) pass 2: agg2[dst] += relu(agg1[src] * w1)
    scatter_kernel<true><<<blocks, threads>>>(src4, dst4, agg1, w1, agg2,
                                              n_quads, n_edges);

    // 4) epilogue (vectorized)
    {
        int eblocks = ((n_nodes >> 2) + 255) / 256;
        if (eblocks > 2048) eblocks = 2048;
        if (eblocks < 1) eblocks = 1;
        epilogue_kernel<<<eblocks, 256>>>(w2, agg2, out, n_nodes);
    }
}